// round 1
// baseline (speedup 1.0000x reference)
#include <cuda_runtime.h>
#include <cuda_fp16.h>

// Problem constants
// B=64, T=1000, C=64, F=5, G=2, H(STEP)=160, 4H=640, D=C*F=320

#define NB   64
#define NT   1000
#define ND   320
#define NH   160
#define N4H  640

// ---------------- static device scratch (no cudaMalloc allowed) --------------
__device__ float  g_x[20480000];       // [B,T,D]  stage input (transposed / gathered)   82MB
__device__ float  g_out1[20480000];    // [B,T,D]  stage-1 hidden output                 82MB
__device__ float  g_xproj[81920000];   // [B,T,G,4H] gate preactivations (x@Wih + b)    328MB
__device__ __half g_wh[409600];        // [stage][group][160][640] fp16 Whh              0.8MB

// ---------------- transpose: input[B,C,T,F] -> g_x[B,T,C*F] ------------------
__global__ void k_transpose(const float* __restrict__ inp) {
    int idx = blockIdx.x * blockDim.x + threadIdx.x;
    if (idx >= 20480000) return;
    int b   = idx / 320000;
    int rem = idx - b * 320000;
    int t   = rem / ND;
    int d   = rem - t * ND;
    g_x[idx] = inp[((size_t)(b * 64 + d / 5) * 1000 + t) * 5 + (d % 5)];
}

// ---------------- weight convert: Whh (fp32) -> g_wh (fp16) ------------------
__global__ void k_convert_w(const float* __restrict__ W1, const float* __restrict__ W2) {
    int idx = blockIdx.x * blockDim.x + threadIdx.x;
    if (idx >= 409600) return;
    float v = (idx < 204800) ? W1[idx] : W2[idx - 204800];
    g_wh[idx] = __float2half(v);
}

// ---------------- gather for stage 2: g_x = g_out1[:, :, snd] ----------------
__global__ void k_gather(const int* __restrict__ snd) {
    int idx = blockIdx.x * blockDim.x + threadIdx.x;
    if (idx >= 20480000) return;
    int r = idx / ND;
    int q = idx - r * ND;
    g_x[idx] = g_out1[(size_t)r * ND + snd[q]];
}

// ---------------- xproj GEMM: g_xproj[r][g*640+o] = b[g][o] + sum_k g_x[r][g*160+k]*Wih[g][k][o]
// M=64000, N=640, K=160 per group. Tile 128x64, BK=16, 256 thr, 8x4 microtile.
__global__ __launch_bounds__(256) void k_gemm(const float* __restrict__ Wih,
                                              const float* __restrict__ bias) {
    int g  = blockIdx.z;
    int m0 = blockIdx.x * 128;
    int n0 = blockIdx.y * 64;
    __shared__ float As[16][128];
    __shared__ float Bs[16][64];
    int tid = threadIdx.x;
    int tx = tid & 15, ty = tid >> 4;

    float acc[8][4];
#pragma unroll
    for (int i = 0; i < 8; i++)
#pragma unroll
        for (int j = 0; j < 4; j++) acc[i][j] = 0.f;

    const float* Xg = g_x + (size_t)m0 * ND + g * NH;
    const float* Wg = Wih + (size_t)g * 102400 + n0;
    int lm = tid >> 1, lkq = (tid & 1) * 8;      // A loader: row lm, 8 consecutive k
    int lk = tid >> 4, ln4 = (tid & 15) * 4;     // B loader: row lk, 4 consecutive n

    for (int k0 = 0; k0 < 160; k0 += 16) {
        float4 a0 = *(const float4*)(Xg + (size_t)lm * ND + k0 + lkq);
        float4 a1 = *(const float4*)(Xg + (size_t)lm * ND + k0 + lkq + 4);
        float4 bv = *(const float4*)(Wg + (size_t)(k0 + lk) * N4H + ln4);
        As[lkq + 0][lm] = a0.x; As[lkq + 1][lm] = a0.y;
        As[lkq + 2][lm] = a0.z; As[lkq + 3][lm] = a0.w;
        As[lkq + 4][lm] = a1.x; As[lkq + 5][lm] = a1.y;
        As[lkq + 6][lm] = a1.z; As[lkq + 7][lm] = a1.w;
        *(float4*)&Bs[lk][ln4] = bv;
        __syncthreads();
#pragma unroll
        for (int k = 0; k < 16; k++) {
            float a[8], bb[4];
#pragma unroll
            for (int i = 0; i < 8; i++) a[i] = As[k][ty * 8 + i];
#pragma unroll
            for (int j = 0; j < 4; j++) bb[j] = Bs[k][tx * 4 + j];
#pragma unroll
            for (int i = 0; i < 8; i++)
#pragma unroll
                for (int j = 0; j < 4; j++) acc[i][j] += a[i] * bb[j];
        }
        __syncthreads();
    }
    float4 bia = *(const float4*)(bias + g * N4H + n0 + tx * 4);
#pragma unroll
    for (int i = 0; i < 8; i++) {
        size_t r = (size_t)m0 + ty * 8 + i;
        float4 v;
        v.x = acc[i][0] + bia.x; v.y = acc[i][1] + bia.y;
        v.z = acc[i][2] + bia.z; v.w = acc[i][3] + bia.w;
        *(float4*)(g_xproj + r * 1280 + g * N4H + n0 + tx * 4) = v;
    }
}

// ---------------- persistent recurrent LSTM -----------------------------------
// grid (64 batch, 2 groups), 320 threads. Each thread owns gate cols 2p,2p+1.
// Whh (fp16) resident in smem; h kept as duplicated half2 for HFMA2 dot.
#define SMEM_W   204800                   // 160*320 half2
#define SMEM_H   (SMEM_W)                 // sH: 160 half2 (640B), padded to 1024
#define SMEM_G   (SMEM_W + 1024)          // sG: 640 floats
#define SMEM_TOT (SMEM_W + 1024 + 2560)

__global__ __launch_bounds__(320, 1) void k_lstm(int stage, float* __restrict__ outp,
                                                 int to_bctf) {
    extern __shared__ char smem[];
    __half2* sW = (__half2*)smem;
    __half2* sH = (__half2*)(smem + SMEM_H);
    float*   sG = (float*)(smem + SMEM_G);

    int b = blockIdx.x, g = blockIdx.y;
    int tid = threadIdx.x;
    int p = tid;

    // load this group's Whh into smem (205KB, vectorized)
    {
        const float4* wsrc = (const float4*)(g_wh + (size_t)stage * 204800 + (size_t)g * 102400);
        float4* wdst = (float4*)sW;
        for (int i = tid; i < 12800; i += 320) wdst[i] = wsrc[i];
    }
    if (tid < NH) sH[tid] = __float2half2_rn(0.f);
    __syncthreads();

    const float*  xp  = g_xproj + (size_t)b * 1000 * 1280 + g * N4H;
    const float2* xp2 = (const float2*)xp;   // row stride = 640 float2

    float cst = 0.f;
    size_t obase = 0; int ostride = 0;
    if (tid < NH) {
        int d = g * NH + tid;
        if (to_bctf) { obase = (size_t)b * 320000 + (size_t)(d / 5) * 5000 + (d % 5); ostride = 5; }
        else         { obase = (size_t)b * 320000 + d;                               ostride = ND; }
    }

    float2 xn = xp2[p];   // prefetch t=0
    for (int t = 0; t < NT; t++) {
        float acc0 = xn.x, acc1 = xn.y;
        if (t + 1 < NT) xn = xp2[(size_t)(t + 1) * 640 + p];   // prefetch next step

        // dot: gates[2p,2p+1] += sum_j h[j] * W[j][2p,2p+1]  (fp16 chunks of 16)
#pragma unroll
        for (int jc = 0; jc < 10; jc++) {
            __half2 s = __float2half2_rn(0.f);
#pragma unroll
            for (int u = 0; u < 4; u++) {
                int j0 = jc * 16 + u * 4;
                float4 hv = *(const float4*)(sH + j0);       // 4 duplicated-h half2
                const __half2* hp = (const __half2*)&hv;
                s = __hfma2(sW[(j0 + 0) * 320 + p], hp[0], s);
                s = __hfma2(sW[(j0 + 1) * 320 + p], hp[1], s);
                s = __hfma2(sW[(j0 + 2) * 320 + p], hp[2], s);
                s = __hfma2(sW[(j0 + 3) * 320 + p], hp[3], s);
            }
            float2 f2 = __half22float2(s);
            acc0 += f2.x; acc1 += f2.y;
        }
        sG[2 * p]     = acc0;
        sG[2 * p + 1] = acc1;
        __syncthreads();

        if (tid < NH) {
            float gi = sG[tid], gf = sG[NH + tid], gg = sG[2 * NH + tid], go = sG[3 * NH + tid];
            float iv = 1.f / (1.f + __expf(-gi));
            float fv = 1.f / (1.f + __expf(-gf));
            float gv = 1.f - 2.f / (1.f + __expf(2.f * gg));
            float ov = 1.f / (1.f + __expf(-go));
            cst = fv * cst + iv * gv;
            float tc = 1.f - 2.f / (1.f + __expf(2.f * cst));
            float hv = ov * tc;
            sH[tid] = __float2half2_rn(hv);
            if (to_bctf) outp[obase + (size_t)t * ostride] = hv;
            else         g_out1[obase + (size_t)t * ostride] = hv;
        }
        __syncthreads();
    }
}

// ---------------- launcher ----------------------------------------------------
extern "C" void kernel_launch(void* const* d_in, const int* in_sizes, int n_in,
                              void* d_out, int out_size) {
    const float* input = (const float*)d_in[0];
    const float* Wih1  = (const float*)d_in[1];
    const float* Whh1  = (const float*)d_in[2];
    const float* b1    = (const float*)d_in[3];
    const float* Wih2  = (const float*)d_in[4];
    const float* Whh2  = (const float*)d_in[5];
    const float* b2    = (const float*)d_in[6];
    const int*   snd   = (const int*)d_in[7];
    float* out = (float*)d_out;

    cudaFuncSetAttribute(k_lstm, cudaFuncAttributeMaxDynamicSharedMemorySize, SMEM_TOT);

    k_convert_w<<<(409600 + 255) / 256, 256>>>(Whh1, Whh2);
    k_transpose<<<(20480000 + 255) / 256, 256>>>(input);

    // stage 1
    k_gemm<<<dim3(500, 10, 2), 256>>>(Wih1, b1);
    k_lstm<<<dim3(NB, 2), 320, SMEM_TOT>>>(0, out, 0);

    // stage 2
    k_gather<<<(20480000 + 255) / 256, 256>>>(snd);
    k_gemm<<<dim3(500, 10, 2), 256>>>(Wih2, b2);
    k_lstm<<<dim3(NB, 2), 320, SMEM_TOT>>>(1, out, 1);
}

// round 3
// speedup vs baseline: 1.4752x; 1.4752x over previous
#include <cuda_runtime.h>
#include <cuda_fp16.h>

// B=64, T=1000, C=64, F=5, G=2, H=160, 4H=640, D=320, M=B*T=64000

// ---------------- static device scratch ----------------
__device__ __half g_xT[20480000];     // [D=320][M=64000] k-major GEMM A (stage1: transposed input; stage2: gathered out1)
__device__ __half g_out1h[20480000];  // [M][320] stage-1 hidden (fp16)
__device__ float  g_xproj[81920000];  // [M][1280] gate preacts (x@Wih + b), fp32
__device__ __half g_wh[409600];       // [stage][g][160][640] fp16 Whh
__device__ __half g_wih[409600];      // [stage][g][160][640] fp16 Wih

// ---------------- helpers ----------------
__device__ __forceinline__ unsigned smem_u32(const void* p) {
    unsigned r;
    asm("{ .reg .u64 t; cvta.to.shared.u64 t, %1; cvt.u32.u64 %0, t; }" : "=r"(r) : "l"(p));
    return r;
}

#define LDSM_X4T(r0,r1,r2,r3,a) \
    asm volatile("ldmatrix.sync.aligned.m8n8.x4.trans.shared.b16 {%0,%1,%2,%3}, [%4];" \
        : "=r"(r0),"=r"(r1),"=r"(r2),"=r"(r3) : "r"(a))

#define MMA16816(c0,c1,c2,c3,a0,a1,a2,a3,b0,b1) \
    asm volatile("mma.sync.aligned.m16n8k16.row.col.f32.f16.f16.f32 " \
        "{%0,%1,%2,%3}, {%4,%5,%6,%7}, {%8,%9}, {%0,%1,%2,%3};" \
        : "+f"(c0),"+f"(c1),"+f"(c2),"+f"(c3) \
        : "r"(a0),"r"(a1),"r"(a2),"r"(a3),"r"(b0),"r"(b1))

// ---------------- weight convert fp32 -> fp16 ----------------
__global__ void k_convert(const float* __restrict__ Wi1, const float* __restrict__ Wi2,
                          const float* __restrict__ Wh1, const float* __restrict__ Wh2) {
    int i = blockIdx.x * blockDim.x + threadIdx.x;
    if (i >= 819200) return;
    if (i < 204800)      g_wih[i]          = __float2half(Wi1[i]);
    else if (i < 409600) g_wih[i]          = __float2half(Wi2[i - 204800]);
    else if (i < 614400) g_wh[i - 409600]  = __float2half(Wh1[i - 409600]);
    else                 g_wh[i - 409600]  = __float2half(Wh2[i - 614400]);
}

// ---------------- transpose: input[B,C,T,F] -> g_xT[d][m] fp16 ----------------
// grid (64 b, 20 t-chunks of 50), 256 thr. smem tile [50 t][322 d-pad].
__global__ __launch_bounds__(256) void k_transpose(const float* __restrict__ inp) {
    __shared__ __half sT[50 * 322];
    int b = blockIdx.x, t0 = blockIdx.y * 50;
    int tid = threadIdx.x;
    // load: per ch, 250 floats (50 t x 5 f) contiguous; read as 125 float2
    for (int i = tid; i < 8000; i += 256) {
        int ch = i / 125, j = i % 125;
        float2 v = *(const float2*)(inp + (size_t)(b * 64 + ch) * 5000 + t0 * 5 + j * 2);
        int e0 = j * 2, e1 = e0 + 1;
        sT[(e0 / 5) * 322 + ch * 5 + (e0 % 5)] = __float2half(v.x);
        sT[(e1 / 5) * 322 + ch * 5 + (e1 % 5)] = __float2half(v.y);
    }
    __syncthreads();
    for (int i = tid; i < 16000; i += 256) {
        int d = i / 50, t = i % 50;
        g_xT[(size_t)d * 64000 + (size_t)b * 1000 + t0 + t] = sT[t * 322 + d];
    }
}

// ---------------- gather: g_xT[d'][m] = out1h[m][snd[d']] ----------------
// grid 1000 m-tiles of 64, 256 thr.
__global__ __launch_bounds__(256) void k_gather(const int* __restrict__ snd) {
    __shared__ __half sT[64 * 322];
    __shared__ int ssnd[320];
    int m0 = blockIdx.x * 64;
    int tid = threadIdx.x;
    for (int c = tid; c < 2560; c += 256) {
        int m = c / 40, ch = c % 40;
        uint4 v = *(const uint4*)(g_out1h + (size_t)(m0 + m) * 320 + ch * 8);
        unsigned* dst = (unsigned*)(sT + m * 322 + ch * 8);
        dst[0] = v.x; dst[1] = v.y; dst[2] = v.z; dst[3] = v.w;
    }
    for (int i = tid; i < 320; i += 256) ssnd[i] = snd[i];
    __syncthreads();
    for (int i = tid; i < 20480; i += 256) {
        int d = i / 64, m = i % 64;
        g_xT[(size_t)d * 64000 + m0 + m] = sT[m * 322 + ssnd[d]];
    }
}

// ---------------- tensor-core xproj GEMM ----------------
// C[M,640]_g = A[M,160]_g (fp16, k-major in smem) x Wih_g[160,640] (fp16) + bias, fp32 out.
// CTA: M=128, N=320 (half of 640), K=160 fully resident. 256 thr = 8 warps, warp = 16 rows x 320 cols.
#define GEMM_SMEM (40960 + 102400)
__global__ __launch_bounds__(256) void k_gemm(int stage, const float* __restrict__ bias) {
    int g = blockIdx.z, nb = blockIdx.y * 320, m0 = blockIdx.x * 128;
    extern __shared__ __half gs[];
    __half* sA = gs;            // [160][128] halves, row 256B = 16 chunks, swizzle chunk^(k&7)
    __half* sB = gs + 20480;    // [160][320] halves, row 640B = 40 chunks, swizzle chunk^(k&7)
    unsigned sAu = smem_u32(sA), sBu = smem_u32(sB);
    int tid = threadIdx.x;
    const __half* Ag = g_xT + (size_t)g * 160 * 64000;
    const __half* Wg = g_wih + (size_t)stage * 204800 + (size_t)g * 102400;
    for (int c = tid; c < 2560; c += 256) {
        int k = c >> 4, cm = c & 15;
        uint4 v = *(const uint4*)(Ag + (size_t)k * 64000 + m0 + cm * 8);
        *(uint4*)((char*)sA + k * 256 + ((cm ^ (k & 7)) << 4)) = v;
    }
    for (int c = tid; c < 6400; c += 256) {
        int k = c / 40, ch = c % 40;
        uint4 v = *(const uint4*)(Wg + (size_t)k * 640 + nb + ch * 8);
        *(uint4*)((char*)sB + k * 640 + ((ch ^ (k & 7)) << 4)) = v;
    }
    __syncthreads();

    int w = tid >> 5, l = tid & 31;
    // A-frag lane address (A stored k-major, ldmatrix.x4.trans)
    unsigned aAddr = sAu + ((l & 7) + ((l >> 4) << 3)) * 256
                         + (((w * 2 + ((l >> 3) & 1)) ^ (l & 7)) << 4);
    unsigned bRow = sBu + (l & 15) * 640;
    int bl = l & 7, bhi = l >> 4;

    for (int it = 0; it < 10; it++) {
        float acc[16];
#pragma unroll
        for (int i = 0; i < 16; i++) acc[i] = 0.f;
#pragma unroll
        for (int ks = 0; ks < 10; ks++) {
            unsigned a0, a1, a2, a3, b0, b1, b2, b3, b4, b5, b6, b7;
            LDSM_X4T(a0, a1, a2, a3, aAddr + ks * 16 * 256);
            int c0 = it * 4 + bhi;
            LDSM_X4T(b0, b1, b2, b3, bRow + ks * 16 * 640 + ((c0 ^ bl) << 4));
            int c1 = it * 4 + 2 + bhi;
            LDSM_X4T(b4, b5, b6, b7, bRow + ks * 16 * 640 + ((c1 ^ bl) << 4));
            MMA16816(acc[0], acc[1], acc[2], acc[3],  a0, a1, a2, a3, b0, b1);
            MMA16816(acc[4], acc[5], acc[6], acc[7],  a0, a1, a2, a3, b2, b3);
            MMA16816(acc[8], acc[9], acc[10], acc[11], a0, a1, a2, a3, b4, b5);
            MMA16816(acc[12], acc[13], acc[14], acc[15], a0, a1, a2, a3, b6, b7);
        }
        int row0 = m0 + w * 16 + (l >> 2);
        int col = g * 640 + nb + it * 32 + (l & 3) * 2;
#pragma unroll
        for (int ch = 0; ch < 4; ch++) {
            int c = col + ch * 8;
            float2 bv = *(const float2*)(bias + c);
            float2 v0 = { acc[ch * 4 + 0] + bv.x, acc[ch * 4 + 1] + bv.y };
            float2 v1 = { acc[ch * 4 + 2] + bv.x, acc[ch * 4 + 3] + bv.y };
            *(float2*)(g_xproj + (size_t)row0 * 1280 + c) = v0;
            *(float2*)(g_xproj + (size_t)(row0 + 8) * 1280 + c) = v1;
        }
    }
}

// ---------------- persistent recurrent LSTM ----------------
// grid (64 b, 2 g), 320 thr. Whh rows 0..63 in regs, rows 64..159 in smem.
#define LSM_W   (96 * 320 * 4)          // 122880 bytes: 96 rows x 320 half2
#define LSM_H   LSM_W
#define LSM_G   (LSM_W + 1024)
#define LSM_TOT (LSM_W + 1024 + 2560)

__global__ __launch_bounds__(320, 1) void k_lstm(int stage, float* __restrict__ outp,
                                                 int to_bctf) {
    extern __shared__ char smem[];
    __half2* sW = (__half2*)smem;               // rows 64..159
    __half2* sH = (__half2*)(smem + LSM_H);     // 160 duplicated-h half2
    float*   sG = (float*)(smem + LSM_G);       // 640 gate preacts

    int b = blockIdx.x, g = blockIdx.y;
    int tid = threadIdx.x, p = tid;

    const __half2* gw = (const __half2*)g_wh + (size_t)stage * 102400 + (size_t)g * 51200;
    __half2 rw[64];
#pragma unroll
    for (int j = 0; j < 64; j++) rw[j] = gw[j * 320 + p];
    {
        const float4* wsrc = (const float4*)(gw + 64 * 320);
        float4* wdst = (float4*)sW;
        for (int i = tid; i < 7680; i += 320) wdst[i] = wsrc[i];
    }
    if (tid < 160) sH[tid] = __float2half2_rn(0.f);
    __syncthreads();

    const float2* xp2 = (const float2*)(g_xproj + (size_t)b * 1000 * 1280 + g * 640);
    float cst = 0.f;
    size_t obase = 0;
    if (tid < 160) {
        int d = g * 160 + tid;
        if (to_bctf) obase = (size_t)b * 320000 + (size_t)(d / 5) * 5000 + (d % 5);
        else         obase = (size_t)b * 320000 + d;    // halves into g_out1h
    }

    float2 xn = xp2[p];
    for (int t = 0; t < 1000; t++) {
        float acc0 = xn.x, acc1 = xn.y;
        if (t + 1 < 1000) xn = xp2[(size_t)(t + 1) * 640 + p];

        // rows 0..63 from registers
#pragma unroll
        for (int jc = 0; jc < 4; jc++) {
            __half2 s = __float2half2_rn(0.f);
#pragma unroll
            for (int u = 0; u < 4; u++) {
                int j0 = jc * 16 + u * 4;
                float4 hv = *(const float4*)(sH + j0);
                const __half2* hp = (const __half2*)&hv;
                s = __hfma2(rw[j0 + 0], hp[0], s);
                s = __hfma2(rw[j0 + 1], hp[1], s);
                s = __hfma2(rw[j0 + 2], hp[2], s);
                s = __hfma2(rw[j0 + 3], hp[3], s);
            }
            float2 f2 = __half22float2(s);
            acc0 += f2.x; acc1 += f2.y;
        }
        // rows 64..159 from smem
#pragma unroll
        for (int jc = 0; jc < 6; jc++) {
            __half2 s = __float2half2_rn(0.f);
#pragma unroll
            for (int u = 0; u < 4; u++) {
                int jr = jc * 16 + u * 4;
                float4 hv = *(const float4*)(sH + 64 + jr);
                const __half2* hp = (const __half2*)&hv;
                s = __hfma2(sW[(jr + 0) * 320 + p], hp[0], s);
                s = __hfma2(sW[(jr + 1) * 320 + p], hp[1], s);
                s = __hfma2(sW[(jr + 2) * 320 + p], hp[2], s);
                s = __hfma2(sW[(jr + 3) * 320 + p], hp[3], s);
            }
            float2 f2 = __half22float2(s);
            acc0 += f2.x; acc1 += f2.y;
        }
        sG[2 * p]     = acc0;
        sG[2 * p + 1] = acc1;
        __syncthreads();

        if (tid < 160) {
            float gi = sG[tid], gf = sG[160 + tid], gg = sG[320 + tid], go = sG[480 + tid];
            float iv = 1.f / (1.f + __expf(-gi));
            float fv = 1.f / (1.f + __expf(-gf));
            float gv = 1.f - 2.f / (1.f + __expf(2.f * gg));
            float ov = 1.f / (1.f + __expf(-go));
            cst = fv * cst + iv * gv;
            float tc = 1.f - 2.f / (1.f + __expf(2.f * cst));
            float hv = ov * tc;
            sH[tid] = __float2half2_rn(hv);
            if (to_bctf) outp[obase + (size_t)t * 5] = hv;
            else         g_out1h[obase + (size_t)t * 320] = __float2half(hv);
        }
        __syncthreads();
    }
}

// ---------------- launcher ----------------
extern "C" void kernel_launch(void* const* d_in, const int* in_sizes, int n_in,
                              void* d_out, int out_size) {
    const float* input = (const float*)d_in[0];
    const float* Wih1  = (const float*)d_in[1];
    const float* Whh1  = (const float*)d_in[2];
    const float* b1    = (const float*)d_in[3];
    const float* Wih2  = (const float*)d_in[4];
    const float* Whh2  = (const float*)d_in[5];
    const float* b2    = (const float*)d_in[6];
    const int*   snd   = (const int*)d_in[7];
    float* out = (float*)d_out;

    cudaFuncSetAttribute(k_gemm, cudaFuncAttributeMaxDynamicSharedMemorySize, GEMM_SMEM);
    cudaFuncSetAttribute(k_lstm, cudaFuncAttributeMaxDynamicSharedMemorySize, LSM_TOT);

    k_convert<<<(819200 + 255) / 256, 256>>>(Wih1, Wih2, Whh1, Whh2);
    k_transpose<<<dim3(64, 20), 256>>>(input);

    // stage 1
    k_gemm<<<dim3(500, 2, 2), 256, GEMM_SMEM>>>(0, b1);
    k_lstm<<<dim3(64, 2), 320, LSM_TOT>>>(0, out, 0);

    // stage 2
    k_gather<<<1000, 256>>>(snd);
    k_gemm<<<dim3(500, 2, 2), 256, GEMM_SMEM>>>(1, b2);
    k_lstm<<<dim3(64, 2), 320, LSM_TOT>>>(1, out, 1);
}

// round 6
// speedup vs baseline: 1.5211x; 1.0311x over previous
#include <cuda_runtime.h>
#include <cuda_fp16.h>

// B=64, T=1000, C=64, F=5, G=2, H=160, 4H=640, D=320, M=B*T=64000

// ---------------- static device scratch ----------------
__device__ __half g_xT[20480000];     // [D=320][M=64000] k-major GEMM A
__device__ __half g_out1h[20480000];  // [M][320] stage-1 hidden (fp16)
__device__ float  g_xproj[81920000];  // [M][1280] gate preacts (x@Wih + b), fp32
__device__ __half g_wh[409600];       // [stage][g][160][640] fp16 Whh
__device__ __half g_wih[409600];      // [stage][g][160][640] fp16 Wih

// ---------------- helpers ----------------
__device__ __forceinline__ unsigned smem_u32(const void* p) {
    unsigned r;
    asm("{ .reg .u64 t; cvta.to.shared.u64 t, %1; cvt.u32.u64 %0, t; }" : "=r"(r) : "l"(p));
    return r;
}

#define LDSM_X4T(r0,r1,r2,r3,a) \
    asm volatile("ldmatrix.sync.aligned.m8n8.x4.trans.shared.b16 {%0,%1,%2,%3}, [%4];" \
        : "=r"(r0),"=r"(r1),"=r"(r2),"=r"(r3) : "r"(a))

#define MMA16816(c0,c1,c2,c3,a0,a1,a2,a3,b0,b1) \
    asm volatile("mma.sync.aligned.m16n8k16.row.col.f32.f16.f16.f32 " \
        "{%0,%1,%2,%3}, {%4,%5,%6,%7}, {%8,%9}, {%0,%1,%2,%3};" \
        : "+f"(c0),"+f"(c1),"+f"(c2),"+f"(c3) \
        : "r"(a0),"r"(a1),"r"(a2),"r"(a3),"r"(b0),"r"(b1))

// ---------------- weight convert fp32 -> fp16 ----------------
__global__ void k_convert(const float* __restrict__ Wi1, const float* __restrict__ Wi2,
                          const float* __restrict__ Wh1, const float* __restrict__ Wh2) {
    int i = blockIdx.x * blockDim.x + threadIdx.x;
    if (i >= 819200) return;
    if (i < 204800)      g_wih[i]          = __float2half(Wi1[i]);
    else if (i < 409600) g_wih[i]          = __float2half(Wi2[i - 204800]);
    else if (i < 614400) g_wh[i - 409600]  = __float2half(Wh1[i - 409600]);
    else                 g_wh[i - 409600]  = __float2half(Wh2[i - 614400]);
}

// ---------------- transpose: input[B,C,T,F] -> g_xT[d][m] fp16 ----------------
__global__ __launch_bounds__(256) void k_transpose(const float* __restrict__ inp) {
    __shared__ __half sT[50 * 322];
    int b = blockIdx.x, t0 = blockIdx.y * 50;
    int tid = threadIdx.x;
    for (int i = tid; i < 8000; i += 256) {
        int ch = i / 125, j = i % 125;
        float2 v = *(const float2*)(inp + (size_t)(b * 64 + ch) * 5000 + t0 * 5 + j * 2);
        int e0 = j * 2, e1 = e0 + 1;
        sT[(e0 / 5) * 322 + ch * 5 + (e0 % 5)] = __float2half(v.x);
        sT[(e1 / 5) * 322 + ch * 5 + (e1 % 5)] = __float2half(v.y);
    }
    __syncthreads();
    for (int i = tid; i < 16000; i += 256) {
        int d = i / 50, t = i % 50;
        g_xT[(size_t)d * 64000 + (size_t)b * 1000 + t0 + t] = sT[t * 322 + d];
    }
}

// ---------------- gather: g_xT[d'][m] = out1h[m][snd[d']] ----------------
__global__ __launch_bounds__(256) void k_gather(const int* __restrict__ snd) {
    __shared__ __half sT[64 * 322];
    __shared__ int ssnd[320];
    int m0 = blockIdx.x * 64;
    int tid = threadIdx.x;
    for (int c = tid; c < 2560; c += 256) {
        int m = c / 40, ch = c % 40;
        uint4 v = *(const uint4*)(g_out1h + (size_t)(m0 + m) * 320 + ch * 8);
        unsigned* dst = (unsigned*)(sT + m * 322 + ch * 8);
        dst[0] = v.x; dst[1] = v.y; dst[2] = v.z; dst[3] = v.w;
    }
    for (int i = tid; i < 320; i += 256) ssnd[i] = snd[i];
    __syncthreads();
    for (int i = tid; i < 20480; i += 256) {
        int d = i / 64, m = i % 64;
        g_xT[(size_t)d * 64000 + m0 + m] = sT[m * 322 + ssnd[d]];
    }
}

// ---------------- tensor-core xproj GEMM ----------------
#define GEMM_SMEM (40960 + 102400)
__global__ __launch_bounds__(256) void k_gemm(int stage, const float* __restrict__ bias) {
    int g = blockIdx.z, nb = blockIdx.y * 320, m0 = blockIdx.x * 128;
    extern __shared__ __half gs[];
    __half* sA = gs;            // [160][128] halves, swizzled
    __half* sB = gs + 20480;    // [160][320] halves, swizzled
    unsigned sAu = smem_u32(sA), sBu = smem_u32(sB);
    int tid = threadIdx.x;
    const __half* Ag = g_xT + (size_t)g * 160 * 64000;
    const __half* Wg = g_wih + (size_t)stage * 204800 + (size_t)g * 102400;
    for (int c = tid; c < 2560; c += 256) {
        int k = c >> 4, cm = c & 15;
        uint4 v = *(const uint4*)(Ag + (size_t)k * 64000 + m0 + cm * 8);
        *(uint4*)((char*)sA + k * 256 + ((cm ^ (k & 7)) << 4)) = v;
    }
    for (int c = tid; c < 6400; c += 256) {
        int k = c / 40, ch = c % 40;
        uint4 v = *(const uint4*)(Wg + (size_t)k * 640 + nb + ch * 8);
        *(uint4*)((char*)sB + k * 640 + ((ch ^ (k & 7)) << 4)) = v;
    }
    __syncthreads();

    int w = tid >> 5, l = tid & 31;
    unsigned aAddr = sAu + ((l & 7) + ((l >> 4) << 3)) * 256
                         + (((w * 2 + ((l >> 3) & 1)) ^ (l & 7)) << 4);
    unsigned bRow = sBu + (l & 15) * 640;
    int bl = l & 7, bhi = l >> 4;

    for (int it = 0; it < 10; it++) {
        float acc[16];
#pragma unroll
        for (int i = 0; i < 16; i++) acc[i] = 0.f;
#pragma unroll
        for (int ks = 0; ks < 10; ks++) {
            unsigned a0, a1, a2, a3, b0, b1, b2, b3, b4, b5, b6, b7;
            LDSM_X4T(a0, a1, a2, a3, aAddr + ks * 16 * 256);
            int c0 = it * 4 + bhi;
            LDSM_X4T(b0, b1, b2, b3, bRow + ks * 16 * 640 + ((c0 ^ bl) << 4));
            int c1 = it * 4 + 2 + bhi;
            LDSM_X4T(b4, b5, b6, b7, bRow + ks * 16 * 640 + ((c1 ^ bl) << 4));
            MMA16816(acc[0], acc[1], acc[2], acc[3],  a0, a1, a2, a3, b0, b1);
            MMA16816(acc[4], acc[5], acc[6], acc[7],  a0, a1, a2, a3, b2, b3);
            MMA16816(acc[8], acc[9], acc[10], acc[11], a0, a1, a2, a3, b4, b5);
            MMA16816(acc[12], acc[13], acc[14], acc[15], a0, a1, a2, a3, b6, b7);
        }
        int row0 = m0 + w * 16 + (l >> 2);
        int col = g * 640 + nb + it * 32 + (l & 3) * 2;
#pragma unroll
        for (int ch = 0; ch < 4; ch++) {
            int c = col + ch * 8;
            float2 bv = *(const float2*)(bias + c);
            float2 v0 = { acc[ch * 4 + 0] + bv.x, acc[ch * 4 + 1] + bv.y };
            float2 v1 = { acc[ch * 4 + 2] + bv.x, acc[ch * 4 + 3] + bv.y };
            *(float2*)(g_xproj + (size_t)row0 * 1280 + c) = v0;
            *(float2*)(g_xproj + (size_t)(row0 + 8) * 1280 + c) = v1;
        }
    }
}

// ---------------- persistent recurrent LSTM (v3) ----------------
// grid (64 b, 2 g), 640 threads = 2 halves x 320 col-pairs.
// Half h owns rows [h*80, h*80+80): 40 rows in registers, 40 rows streamed
// from smem pair-packed (LDS.64 = 2 rows). Partials summed in smem.
#define LS_W   102400                       // 2 halves x 20 pairs x 320 uint2
#define LS_H   LS_W                         // sH: 160 half2 (640B), pad 1024
#define LS_G   (LS_W + 1024)                // sG: [2][640] floats

__global__ __launch_bounds__(640, 1) void k_lstm(int stage, float* __restrict__ outp,
                                                 int to_bctf) {
    extern __shared__ char smem[];
    uint2*   sW = (uint2*)smem;
    __half2* sH = (__half2*)(smem + LS_H);
    float*   sG = (float*)(smem + LS_G);

    int b = blockIdx.x, g = blockIdx.y;
    int tid = threadIdx.x;
    int half = tid >= 320 ? 1 : 0;
    int p = tid - half * 320;
    int hbase = half * 80;

    const __half2* gw = (const __half2*)g_wh + (size_t)stage * 102400 + (size_t)g * 51200;
    const unsigned* gwu = (const unsigned*)gw;

    // register rows hbase..hbase+39
    __half2 rw[40];
#pragma unroll
    for (int j = 0; j < 40; j++) rw[j] = gw[(hbase + j) * 320 + p];

    // streamed rows hbase+40..hbase+79, pair-packed into smem
    for (int i = tid; i < 12800; i += 640) {
        int hh = i / 6400, rem = i - hh * 6400;
        int q = rem / 320, pp = rem - q * 320;
        int row = hh * 80 + 40 + 2 * q;
        uint2 v;
        v.x = gwu[row * 320 + pp];
        v.y = gwu[(row + 1) * 320 + pp];
        sW[(hh * 20 + q) * 320 + pp] = v;
    }
    if (tid < 160) sH[tid] = __float2half2_rn(0.f);
    __syncthreads();

    const float2* xp2 = (const float2*)(g_xproj + (size_t)b * 1000 * 1280 + g * 640);
    float cst = 0.f;
    size_t obase = 0;
    if (tid < 160) {
        int d = g * 160 + tid;
        if (to_bctf) obase = (size_t)b * 320000 + (size_t)(d / 5) * 5000 + (d % 5);
        else         obase = (size_t)b * 320000 + d;
    }

    const uint2* wbase = sW + (half * 20) * 320 + p;
    float2 xn = make_float2(0.f, 0.f);
    if (half == 0) xn = xp2[p];

    for (int t = 0; t < 1000; t++) {
        float acc0 = xn.x, acc1 = xn.y;
        if (half == 0 && t + 1 < 1000) xn = xp2[(size_t)(t + 1) * 640 + p];

        // register rows: 5 chunks of 8
#pragma unroll
        for (int c = 0; c < 5; c++) {
            int j0 = hbase + c * 8;
            float4 hA = *(const float4*)(sH + j0);
            float4 hB = *(const float4*)(sH + j0 + 4);
            const __half2* hp = (const __half2*)&hA;
            const __half2* hq = (const __half2*)&hB;
            __half2 s = __float2half2_rn(0.f);
            s = __hfma2(rw[c * 8 + 0], hp[0], s);
            s = __hfma2(rw[c * 8 + 1], hp[1], s);
            s = __hfma2(rw[c * 8 + 2], hp[2], s);
            s = __hfma2(rw[c * 8 + 3], hp[3], s);
            s = __hfma2(rw[c * 8 + 4], hq[0], s);
            s = __hfma2(rw[c * 8 + 5], hq[1], s);
            s = __hfma2(rw[c * 8 + 6], hq[2], s);
            s = __hfma2(rw[c * 8 + 7], hq[3], s);
            float2 f2 = __half22float2(s);
            acc0 += f2.x; acc1 += f2.y;
        }
        // smem rows: 5 chunks of 8 (4 pair-packed LDS.64 each)
#pragma unroll
        for (int c = 0; c < 5; c++) {
            int j0 = hbase + 40 + c * 8;
            float4 hA = *(const float4*)(sH + j0);
            float4 hB = *(const float4*)(sH + j0 + 4);
            const __half2* hp = (const __half2*)&hA;
            const __half2* hq = (const __half2*)&hB;
            uint2 w0 = wbase[(c * 4 + 0) * 320];
            uint2 w1 = wbase[(c * 4 + 1) * 320];
            uint2 w2 = wbase[(c * 4 + 2) * 320];
            uint2 w3 = wbase[(c * 4 + 3) * 320];
            __half2 s = __float2half2_rn(0.f);
            s = __hfma2(*(__half2*)&w0.x, hp[0], s);
            s = __hfma2(*(__half2*)&w0.y, hp[1], s);
            s = __hfma2(*(__half2*)&w1.x, hp[2], s);
            s = __hfma2(*(__half2*)&w1.y, hp[3], s);
            s = __hfma2(*(__half2*)&w2.x, hq[0], s);
            s = __hfma2(*(__half2*)&w2.y, hq[1], s);
            s = __hfma2(*(__half2*)&w3.x, hq[2], s);
            s = __hfma2(*(__half2*)&w3.y, hq[3], s);
            float2 f2 = __half22float2(s);
            acc0 += f2.x; acc1 += f2.y;
        }
        *(float2*)(sG + half * 640 + 2 * p) = make_float2(acc0, acc1);
        __syncthreads();

        if (tid < 160) {
            float gi = sG[tid]       + sG[640 + tid];
            float gf = sG[160 + tid] + sG[800 + tid];
            float gg = sG[320 + tid] + sG[960 + tid];
            float go = sG[480 + tid] + sG[1120 + tid];
            float iv = 1.f / (1.f + __expf(-gi));
            float fv = 1.f / (1.f + __expf(-gf));
            float gv = 1.f - 2.f / (1.f + __expf(2.f * gg));
            float ov = 1.f / (1.f + __expf(-go));
            cst = fv * cst + iv * gv;
            float tc = 1.f - 2.f / (1.f + __expf(2.f * cst));
            float hv = ov * tc;
            sH[tid] = __float2half2_rn(hv);
            if (to_bctf) outp[obase + (size_t)t * 5] = hv;
            else         g_out1h[obase + (size_t)t * 320] = __float2half(hv);
        }
        __syncthreads();
    }
}

// ---------------- launcher ----------------
extern "C" void kernel_launch(void* const* d_in, const int* in_sizes, int n_in,
                              void* d_out, int out_size) {
    const float* input = (const float*)d_in[0];
    const float* Wih1  = (const float*)d_in[1];
    const float* Whh1  = (const float*)d_in[2];
    const float* b1    = (const float*)d_in[3];
    const float* Wih2  = (const float*)d_in[4];
    const float* Whh2  = (const float*)d_in[5];
    const float* b2    = (const float*)d_in[6];
    const int*   snd   = (const int*)d_in[7];
    float* out = (float*)d_out;

    cudaFuncSetAttribute(k_gemm, cudaFuncAttributeMaxDynamicSharedMemorySize, GEMM_SMEM);
    cudaFuncSetAttribute(k_lstm, cudaFuncAttributeMaxDynamicSharedMemorySize, LS_G + 5120);

    k_convert<<<(819200 + 255) / 256, 256>>>(Wih1, Wih2, Whh1, Whh2);
    k_transpose<<<dim3(64, 20), 256>>>(input);

    // stage 1
    k_gemm<<<dim3(500, 2, 2), 256, GEMM_SMEM>>>(0, b1);
    k_lstm<<<dim3(64, 2), 640, LS_G + 5120>>>(0, out, 0);

    // stage 2
    k_gather<<<1000, 256>>>(snd);
    k_gemm<<<dim3(500, 2, 2), 256, GEMM_SMEM>>>(1, b2);
    k_lstm<<<dim3(64, 2), 640, LS_G + 5120>>>(1, out, 1);
}

// round 7
// speedup vs baseline: 1.7438x; 1.1464x over previous
#include <cuda_runtime.h>
#include <cuda_fp16.h>

// B=64, T=1000, C=64, F=5, G=2, H=160, 4H=640, D=320, M=B*T=64000

// ---------------- static device scratch ----------------
__device__ __half g_xT[20480000];     // [D=320][M=64000] k-major GEMM A
__device__ __half g_out1h[20480000];  // [M][320] stage-1 hidden (fp16)
__device__ float  g_xproj[81920000];  // [M][1280] gate preacts (x@Wih + b), fp32
__device__ __half g_wh[409600];       // [stage][g][160][640] fp16 Whh
__device__ __half g_wih[409600];      // [stage][g][160][640] fp16 Wih

// ---------------- helpers ----------------
__device__ __forceinline__ unsigned smem_u32(const void* p) {
    unsigned r;
    asm("{ .reg .u64 t; cvta.to.shared.u64 t, %1; cvt.u32.u64 %0, t; }" : "=r"(r) : "l"(p));
    return r;
}

#define LDSM_X4T(r0,r1,r2,r3,a) \
    asm volatile("ldmatrix.sync.aligned.m8n8.x4.trans.shared.b16 {%0,%1,%2,%3}, [%4];" \
        : "=r"(r0),"=r"(r1),"=r"(r2),"=r"(r3) : "r"(a))

#define MMA16816(c0,c1,c2,c3,a0,a1,a2,a3,b0,b1) \
    asm volatile("mma.sync.aligned.m16n8k16.row.col.f32.f16.f16.f32 " \
        "{%0,%1,%2,%3}, {%4,%5,%6,%7}, {%8,%9}, {%0,%1,%2,%3};" \
        : "+f"(c0),"+f"(c1),"+f"(c2),"+f"(c3) \
        : "r"(a0),"r"(a1),"r"(a2),"r"(a3),"r"(b0),"r"(b1))

// ---------------- weight convert fp32 -> fp16 ----------------
__global__ void k_convert(const float* __restrict__ Wi1, const float* __restrict__ Wi2,
                          const float* __restrict__ Wh1, const float* __restrict__ Wh2) {
    int i = blockIdx.x * blockDim.x + threadIdx.x;
    if (i >= 819200) return;
    if (i < 204800)      g_wih[i]          = __float2half(Wi1[i]);
    else if (i < 409600) g_wih[i]          = __float2half(Wi2[i - 204800]);
    else if (i < 614400) g_wh[i - 409600]  = __float2half(Wh1[i - 409600]);
    else                 g_wh[i - 409600]  = __float2half(Wh2[i - 614400]);
}

// ---------------- transpose: input[B,C,T,F] -> g_xT[d][m] fp16 ----------------
__global__ __launch_bounds__(256) void k_transpose(const float* __restrict__ inp) {
    __shared__ __half sT[50 * 322];
    int b = blockIdx.x, t0 = blockIdx.y * 50;
    int tid = threadIdx.x;
    for (int i = tid; i < 8000; i += 256) {
        int ch = i / 125, j = i % 125;
        float2 v = *(const float2*)(inp + (size_t)(b * 64 + ch) * 5000 + t0 * 5 + j * 2);
        int e0 = j * 2, e1 = e0 + 1;
        sT[(e0 / 5) * 322 + ch * 5 + (e0 % 5)] = __float2half(v.x);
        sT[(e1 / 5) * 322 + ch * 5 + (e1 % 5)] = __float2half(v.y);
    }
    __syncthreads();
    for (int i = tid; i < 16000; i += 256) {
        int d = i / 50, t = i % 50;
        g_xT[(size_t)d * 64000 + (size_t)b * 1000 + t0 + t] = sT[t * 322 + d];
    }
}

// ---------------- gather: g_xT[d'][m] = out1h[m][snd[d']] ----------------
__global__ __launch_bounds__(256) void k_gather(const int* __restrict__ snd) {
    __shared__ __half sT[64 * 322];
    __shared__ int ssnd[320];
    int m0 = blockIdx.x * 64;
    int tid = threadIdx.x;
    for (int c = tid; c < 2560; c += 256) {
        int m = c / 40, ch = c % 40;
        uint4 v = *(const uint4*)(g_out1h + (size_t)(m0 + m) * 320 + ch * 8);
        unsigned* dst = (unsigned*)(sT + m * 322 + ch * 8);
        dst[0] = v.x; dst[1] = v.y; dst[2] = v.z; dst[3] = v.w;
    }
    for (int i = tid; i < 320; i += 256) ssnd[i] = snd[i];
    __syncthreads();
    for (int i = tid; i < 20480; i += 256) {
        int d = i / 64, m = i % 64;
        g_xT[(size_t)d * 64000 + m0 + m] = sT[m * 322 + ssnd[d]];
    }
}

// ---------------- tensor-core xproj GEMM ----------------
#define GEMM_SMEM (40960 + 102400)
__global__ __launch_bounds__(256) void k_gemm(int stage, const float* __restrict__ bias) {
    int g = blockIdx.z, nb = blockIdx.y * 320, m0 = blockIdx.x * 128;
    extern __shared__ __half gs[];
    __half* sA = gs;            // [160][128] halves, swizzled
    __half* sB = gs + 20480;    // [160][320] halves, swizzled
    unsigned sAu = smem_u32(sA), sBu = smem_u32(sB);
    int tid = threadIdx.x;
    const __half* Ag = g_xT + (size_t)g * 160 * 64000;
    const __half* Wg = g_wih + (size_t)stage * 204800 + (size_t)g * 102400;
    for (int c = tid; c < 2560; c += 256) {
        int k = c >> 4, cm = c & 15;
        uint4 v = *(const uint4*)(Ag + (size_t)k * 64000 + m0 + cm * 8);
        *(uint4*)((char*)sA + k * 256 + ((cm ^ (k & 7)) << 4)) = v;
    }
    for (int c = tid; c < 6400; c += 256) {
        int k = c / 40, ch = c % 40;
        uint4 v = *(const uint4*)(Wg + (size_t)k * 640 + nb + ch * 8);
        *(uint4*)((char*)sB + k * 640 + ((ch ^ (k & 7)) << 4)) = v;
    }
    __syncthreads();

    int w = tid >> 5, l = tid & 31;
    unsigned aAddr = sAu + ((l & 7) + ((l >> 4) << 3)) * 256
                         + (((w * 2 + ((l >> 3) & 1)) ^ (l & 7)) << 4);
    unsigned bRow = sBu + (l & 15) * 640;
    int bl = l & 7, bhi = l >> 4;

    for (int it = 0; it < 10; it++) {
        float acc[16];
#pragma unroll
        for (int i = 0; i < 16; i++) acc[i] = 0.f;
#pragma unroll
        for (int ks = 0; ks < 10; ks++) {
            unsigned a0, a1, a2, a3, b0, b1, b2, b3, b4, b5, b6, b7;
            LDSM_X4T(a0, a1, a2, a3, aAddr + ks * 16 * 256);
            int c0 = it * 4 + bhi;
            LDSM_X4T(b0, b1, b2, b3, bRow + ks * 16 * 640 + ((c0 ^ bl) << 4));
            int c1 = it * 4 + 2 + bhi;
            LDSM_X4T(b4, b5, b6, b7, bRow + ks * 16 * 640 + ((c1 ^ bl) << 4));
            MMA16816(acc[0], acc[1], acc[2], acc[3],  a0, a1, a2, a3, b0, b1);
            MMA16816(acc[4], acc[5], acc[6], acc[7],  a0, a1, a2, a3, b2, b3);
            MMA16816(acc[8], acc[9], acc[10], acc[11], a0, a1, a2, a3, b4, b5);
            MMA16816(acc[12], acc[13], acc[14], acc[15], a0, a1, a2, a3, b6, b7);
        }
        int row0 = m0 + w * 16 + (l >> 2);
        int col = g * 640 + nb + it * 32 + (l & 3) * 2;
#pragma unroll
        for (int ch = 0; ch < 4; ch++) {
            int c = col + ch * 8;
            float2 bv = *(const float2*)(bias + c);
            float2 v0 = { acc[ch * 4 + 0] + bv.x, acc[ch * 4 + 1] + bv.y };
            float2 v1 = { acc[ch * 4 + 2] + bv.x, acc[ch * 4 + 3] + bv.y };
            *(float2*)(g_xproj + (size_t)row0 * 1280 + c) = v0;
            *(float2*)(g_xproj + (size_t)(row0 + 8) * 1280 + c) = v1;
        }
    }
}

// ---------------- persistent recurrent LSTM (v4) ----------------
// grid (64 b, 2 g), 640 threads = 2 halves x 320 col-pairs.
// Half h owns rows [h*80, h*80+80): 48 rows in registers, 32 rows streamed
// from smem QUAD-packed (LDS.128 = 4 rows). fp16 accumulate in 16-row groups.
#define LS_W   81920                        // 2 halves x 8 quads x 320 uint4
#define LS_H   LS_W                         // sH: 160 half2 (640B), pad 1024
#define LS_G   (LS_W + 1024)                // sG: [2][640] floats
#define LS_TOT (LS_G + 5120)

// 8 rows from registers rw[b..b+7], h rows hbase+b..+7
#define LACC8R(b) { \
    float4 hA = *(const float4*)(sH + hbase + (b)); \
    float4 hB = *(const float4*)(sH + hbase + (b) + 4); \
    const __half2* hp = (const __half2*)&hA; \
    const __half2* hq = (const __half2*)&hB; \
    s = __hfma2(rw[(b)+0], hp[0], s); \
    s = __hfma2(rw[(b)+1], hp[1], s); \
    s = __hfma2(rw[(b)+2], hp[2], s); \
    s = __hfma2(rw[(b)+3], hp[3], s); \
    s = __hfma2(rw[(b)+4], hq[0], s); \
    s = __hfma2(rw[(b)+5], hq[1], s); \
    s = __hfma2(rw[(b)+6], hq[2], s); \
    s = __hfma2(rw[(b)+7], hq[3], s); }

// 8 rows from smem quads qi, qi+1 (rows hbase+48+4*qi .. +7)
#define LACC8S(qi) { \
    float4 hA = *(const float4*)(sH + hbase + 48 + (qi) * 4); \
    float4 hB = *(const float4*)(sH + hbase + 48 + (qi) * 4 + 4); \
    const __half2* hp = (const __half2*)&hA; \
    const __half2* hq = (const __half2*)&hB; \
    uint4 wA = wq[(qi) * 320]; \
    uint4 wB = wq[((qi) + 1) * 320]; \
    s = __hfma2(*(__half2*)&wA.x, hp[0], s); \
    s = __hfma2(*(__half2*)&wA.y, hp[1], s); \
    s = __hfma2(*(__half2*)&wA.z, hp[2], s); \
    s = __hfma2(*(__half2*)&wA.w, hp[3], s); \
    s = __hfma2(*(__half2*)&wB.x, hq[0], s); \
    s = __hfma2(*(__half2*)&wB.y, hq[1], s); \
    s = __hfma2(*(__half2*)&wB.z, hq[2], s); \
    s = __hfma2(*(__half2*)&wB.w, hq[3], s); }

__global__ __launch_bounds__(640, 1) void k_lstm(int stage, float* __restrict__ outp,
                                                 int to_bctf) {
    extern __shared__ char smem[];
    uint4*   sW4 = (uint4*)smem;
    __half2* sH  = (__half2*)(smem + LS_H);
    float*   sG  = (float*)(smem + LS_G);

    int b = blockIdx.x, g = blockIdx.y;
    int tid = threadIdx.x;
    int half = tid >= 320 ? 1 : 0;
    int p = tid - half * 320;
    int hbase = half * 80;

    const __half2* gw = (const __half2*)g_wh + (size_t)stage * 102400 + (size_t)g * 51200;
    const unsigned* gwu = (const unsigned*)gw;

    // register rows hbase..hbase+47
    __half2 rw[48];
#pragma unroll
    for (int j = 0; j < 48; j++) rw[j] = gw[(hbase + j) * 320 + p];

    // streamed rows hbase+48..hbase+79, quad-packed into smem (4 rows per uint4)
    for (int i = tid; i < 5120; i += 640) {
        int hh = i / 2560, rem = i - hh * 2560;
        int q = rem / 320, pp = rem - q * 320;
        int row = hh * 80 + 48 + 4 * q;
        uint4 v;
        v.x = gwu[(row + 0) * 320 + pp];
        v.y = gwu[(row + 1) * 320 + pp];
        v.z = gwu[(row + 2) * 320 + pp];
        v.w = gwu[(row + 3) * 320 + pp];
        sW4[(hh * 8 + q) * 320 + pp] = v;
    }
    if (tid < 160) sH[tid] = __float2half2_rn(0.f);
    __syncthreads();

    const float2* xp2 = (const float2*)(g_xproj + (size_t)b * 1000 * 1280 + g * 640);
    float cst = 0.f;
    size_t obase = 0;
    if (tid < 160) {
        int d = g * 160 + tid;
        if (to_bctf) obase = (size_t)b * 320000 + (size_t)(d / 5) * 5000 + (d % 5);
        else         obase = (size_t)b * 320000 + d;
    }

    const uint4* wq = sW4 + (half * 8) * 320 + p;
    float2 xn = make_float2(0.f, 0.f);
    if (half == 0) xn = xp2[p];

    for (int t = 0; t < 1000; t++) {
        float acc0 = xn.x, acc1 = xn.y;
        if (half == 0 && t + 1 < 1000) xn = xp2[(size_t)(t + 1) * 640 + p];

        __half2 s;
        float2 f2;
        // 5 groups of 16 rows, fp16 accumulation within each group
        s = __float2half2_rn(0.f); LACC8R(0);  LACC8R(8);
        f2 = __half22float2(s); acc0 += f2.x; acc1 += f2.y;
        s = __float2half2_rn(0.f); LACC8R(16); LACC8R(24);
        f2 = __half22float2(s); acc0 += f2.x; acc1 += f2.y;
        s = __float2half2_rn(0.f); LACC8R(32); LACC8R(40);
        f2 = __half22float2(s); acc0 += f2.x; acc1 += f2.y;
        s = __float2half2_rn(0.f); LACC8S(0);  LACC8S(2);
        f2 = __half22float2(s); acc0 += f2.x; acc1 += f2.y;
        s = __float2half2_rn(0.f); LACC8S(4);  LACC8S(6);
        f2 = __half22float2(s); acc0 += f2.x; acc1 += f2.y;

        *(float2*)(sG + half * 640 + 2 * p) = make_float2(acc0, acc1);
        __syncthreads();

        if (tid < 160) {
            float gi = sG[tid]       + sG[640 + tid];
            float gf = sG[160 + tid] + sG[800 + tid];
            float gg = sG[320 + tid] + sG[960 + tid];
            float go = sG[480 + tid] + sG[1120 + tid];
            float iv = __fdividef(1.f, 1.f + __expf(-gi));
            float fv = __fdividef(1.f, 1.f + __expf(-gf));
            float gv = 1.f - __fdividef(2.f, 1.f + __expf(2.f * gg));
            float ov = __fdividef(1.f, 1.f + __expf(-go));
            cst = fv * cst + iv * gv;
            float tc = 1.f - __fdividef(2.f, 1.f + __expf(2.f * cst));
            float hv = ov * tc;
            sH[tid] = __float2half2_rn(hv);
            if (to_bctf) outp[obase + (size_t)t * 5] = hv;
            else         g_out1h[obase + (size_t)t * 320] = __float2half(hv);
        }
        __syncthreads();
    }
}

// ---------------- launcher ----------------
extern "C" void kernel_launch(void* const* d_in, const int* in_sizes, int n_in,
                              void* d_out, int out_size) {
    const float* input = (const float*)d_in[0];
    const float* Wih1  = (const float*)d_in[1];
    const float* Whh1  = (const float*)d_in[2];
    const float* b1    = (const float*)d_in[3];
    const float* Wih2  = (const float*)d_in[4];
    const float* Whh2  = (const float*)d_in[5];
    const float* b2    = (const float*)d_in[6];
    const int*   snd   = (const int*)d_in[7];
    float* out = (float*)d_out;

    cudaFuncSetAttribute(k_gemm, cudaFuncAttributeMaxDynamicSharedMemorySize, GEMM_SMEM);
    cudaFuncSetAttribute(k_lstm, cudaFuncAttributeMaxDynamicSharedMemorySize, LS_TOT);

    k_convert<<<(819200 + 255) / 256, 256>>>(Wih1, Wih2, Whh1, Whh2);
    k_transpose<<<dim3(64, 20), 256>>>(input);

    // stage 1
    k_gemm<<<dim3(500, 2, 2), 256, GEMM_SMEM>>>(0, b1);
    k_lstm<<<dim3(64, 2), 640, LS_TOT>>>(0, out, 0);

    // stage 2
    k_gather<<<1000, 256>>>(snd);
    k_gemm<<<dim3(500, 2, 2), 256, GEMM_SMEM>>>(1, b2);
    k_lstm<<<dim3(64, 2), 640, LS_TOT>>>(1, out, 1);
}

// round 9
// speedup vs baseline: 1.8998x; 1.0895x over previous
#include <cuda_runtime.h>
#include <cuda_fp16.h>

// B=64, T=1000, C=64, F=5, G=2, H=160, 4H=640, D=320, M=B*T=64000

// ---------------- static device scratch ----------------
__device__ __half  g_xT[20480000];     // [D=320][M=64000] k-major GEMM A
__device__ __half  g_out1h[20480000];  // [M][320] stage-1 hidden (fp16)
__device__ float   g_xproj[81920000];  // [M][1280] gate preacts (x@Wih + b), fp32
__device__ __half2 g_wh2[204800];      // [stage][g][80][640] pair-packed Whh: (W[2q][p],W[2q+1][p])
__device__ __half  g_wih[409600];      // [stage][g][160][640] fp16 Wih

// ---------------- helpers ----------------
__device__ __forceinline__ unsigned smem_u32(const void* p) {
    unsigned r;
    asm("{ .reg .u64 t; cvta.to.shared.u64 t, %1; cvt.u32.u64 %0, t; }" : "=r"(r) : "l"(p));
    return r;
}

#define LDSM_X4T(r0,r1,r2,r3,a) \
    asm volatile("ldmatrix.sync.aligned.m8n8.x4.trans.shared.b16 {%0,%1,%2,%3}, [%4];" \
        : "=r"(r0),"=r"(r1),"=r"(r2),"=r"(r3) : "r"(a))

#define MMA16816(c0,c1,c2,c3,a0,a1,a2,a3,b0,b1) \
    asm volatile("mma.sync.aligned.m16n8k16.row.col.f32.f16.f16.f32 " \
        "{%0,%1,%2,%3}, {%4,%5,%6,%7}, {%8,%9}, {%0,%1,%2,%3};" \
        : "+f"(c0),"+f"(c1),"+f"(c2),"+f"(c3) \
        : "r"(a0),"r"(a1),"r"(a2),"r"(a3),"r"(b0),"r"(b1))

// ---------------- weight convert fp32 -> fp16 ----------------
// i < 409600: flat Wih halves. i < 204800 also packs Whh pairs.
__global__ void k_convert(const float* __restrict__ Wi1, const float* __restrict__ Wi2,
                          const float* __restrict__ Wh1, const float* __restrict__ Wh2) {
    int i = blockIdx.x * blockDim.x + threadIdx.x;
    if (i >= 409600) return;
    if (i < 204800) g_wih[i] = __float2half(Wi1[i]);
    else            g_wih[i] = __float2half(Wi2[i - 204800]);
    if (i < 204800) {
        int st = i / 102400, r = i - st * 102400;   // per stage: g*51200 + q*640 + p
        int gg = r / 51200,  r2 = r - gg * 51200;
        int q = r2 / 640,    p = r2 - q * 640;
        const float* W = st ? Wh2 : Wh1;
        float a = W[gg * 102400 + (2 * q) * 640 + p];
        float b = W[gg * 102400 + (2 * q + 1) * 640 + p];
        g_wh2[i] = __halves2half2(__float2half(a), __float2half(b));
    }
}

// ---------------- transpose: input[B,C,T,F] -> g_xT[d][m] fp16 ----------------
__global__ __launch_bounds__(256) void k_transpose(const float* __restrict__ inp) {
    __shared__ __half sT[50 * 322];
    int b = blockIdx.x, t0 = blockIdx.y * 50;
    int tid = threadIdx.x;
    for (int i = tid; i < 8000; i += 256) {
        int ch = i / 125, j = i % 125;
        float2 v = *(const float2*)(inp + (size_t)(b * 64 + ch) * 5000 + t0 * 5 + j * 2);
        int e0 = j * 2, e1 = e0 + 1;
        sT[(e0 / 5) * 322 + ch * 5 + (e0 % 5)] = __float2half(v.x);
        sT[(e1 / 5) * 322 + ch * 5 + (e1 % 5)] = __float2half(v.y);
    }
    __syncthreads();
    for (int i = tid; i < 16000; i += 256) {
        int d = i / 50, t = i % 50;
        g_xT[(size_t)d * 64000 + (size_t)b * 1000 + t0 + t] = sT[t * 322 + d];
    }
}

// ---------------- gather: g_xT[d'][m] = out1h[m][snd[d']] ----------------
__global__ __launch_bounds__(256) void k_gather(const int* __restrict__ snd) {
    __shared__ __half sT[64 * 322];
    __shared__ int ssnd[320];
    int m0 = blockIdx.x * 64;
    int tid = threadIdx.x;
    for (int c = tid; c < 2560; c += 256) {
        int m = c / 40, ch = c % 40;
        uint4 v = *(const uint4*)(g_out1h + (size_t)(m0 + m) * 320 + ch * 8);
        unsigned* dst = (unsigned*)(sT + m * 322 + ch * 8);
        dst[0] = v.x; dst[1] = v.y; dst[2] = v.z; dst[3] = v.w;
    }
    for (int i = tid; i < 320; i += 256) ssnd[i] = snd[i];
    __syncthreads();
    for (int i = tid; i < 20480; i += 256) {
        int d = i / 64, m = i % 64;
        g_xT[(size_t)d * 64000 + m0 + m] = sT[m * 322 + ssnd[d]];
    }
}

// ---------------- tensor-core xproj GEMM ----------------
#define GEMM_SMEM (40960 + 102400)
__global__ __launch_bounds__(256) void k_gemm(int stage, const float* __restrict__ bias) {
    int g = blockIdx.z, nb = blockIdx.y * 320, m0 = blockIdx.x * 128;
    extern __shared__ __half gs[];
    __half* sA = gs;            // [160][128] halves, swizzled
    __half* sB = gs + 20480;    // [160][320] halves, swizzled
    unsigned sAu = smem_u32(sA), sBu = smem_u32(sB);
    int tid = threadIdx.x;
    const __half* Ag = g_xT + (size_t)g * 160 * 64000;
    const __half* Wg = g_wih + (size_t)stage * 204800 + (size_t)g * 102400;
    for (int c = tid; c < 2560; c += 256) {
        int k = c >> 4, cm = c & 15;
        uint4 v = *(const uint4*)(Ag + (size_t)k * 64000 + m0 + cm * 8);
        *(uint4*)((char*)sA + k * 256 + ((cm ^ (k & 7)) << 4)) = v;
    }
    for (int c = tid; c < 6400; c += 256) {
        int k = c / 40, ch = c % 40;
        uint4 v = *(const uint4*)(Wg + (size_t)k * 640 + nb + ch * 8);
        *(uint4*)((char*)sB + k * 640 + ((ch ^ (k & 7)) << 4)) = v;
    }
    __syncthreads();

    int w = tid >> 5, l = tid & 31;
    unsigned aAddr = sAu + ((l & 7) + ((l >> 4) << 3)) * 256
                         + (((w * 2 + ((l >> 3) & 1)) ^ (l & 7)) << 4);
    unsigned bRow = sBu + (l & 15) * 640;
    int bl = l & 7, bhi = l >> 4;

    for (int it = 0; it < 10; it++) {
        float acc[16];
#pragma unroll
        for (int i = 0; i < 16; i++) acc[i] = 0.f;
#pragma unroll
        for (int ks = 0; ks < 10; ks++) {
            unsigned a0, a1, a2, a3, b0, b1, b2, b3, b4, b5, b6, b7;
            LDSM_X4T(a0, a1, a2, a3, aAddr + ks * 16 * 256);
            int c0 = it * 4 + bhi;
            LDSM_X4T(b0, b1, b2, b3, bRow + ks * 16 * 640 + ((c0 ^ bl) << 4));
            int c1 = it * 4 + 2 + bhi;
            LDSM_X4T(b4, b5, b6, b7, bRow + ks * 16 * 640 + ((c1 ^ bl) << 4));
            MMA16816(acc[0], acc[1], acc[2], acc[3],  a0, a1, a2, a3, b0, b1);
            MMA16816(acc[4], acc[5], acc[6], acc[7],  a0, a1, a2, a3, b2, b3);
            MMA16816(acc[8], acc[9], acc[10], acc[11], a0, a1, a2, a3, b4, b5);
            MMA16816(acc[12], acc[13], acc[14], acc[15], a0, a1, a2, a3, b6, b7);
        }
        int row0 = m0 + w * 16 + (l >> 2);
        int col = g * 640 + nb + it * 32 + (l & 3) * 2;
#pragma unroll
        for (int ch = 0; ch < 4; ch++) {
            int c = col + ch * 8;
            float2 bv = *(const float2*)(bias + c);
            float2 v0 = { acc[ch * 4 + 0] + bv.x, acc[ch * 4 + 1] + bv.y };
            float2 v1 = { acc[ch * 4 + 2] + bv.x, acc[ch * 4 + 3] + bv.y };
            *(float2*)(g_xproj + (size_t)row0 * 1280 + c) = v0;
            *(float2*)(g_xproj + (size_t)(row0 + 8) * 1280 + c) = v1;
        }
    }
}

// ---------------- persistent recurrent LSTM (v5) ----------------
// grid (64 b, 2 g), 640 threads; thread p owns gate column p, ALL 160 rows.
// Row pairs packed into half2 lanes: s = hfma2((W[2q],W[2q+1]), (h[2q],h[2q+1])).
// Pairs 0..55 (rows 0..111) in registers; pairs 56..79 (rows 112..159) streamed
// from smem quad-packed (uint4 = 4 pairs). h stored packed half[160] (320B).
#define LS_W   61440                 // 6 quads x 640 uint4
#define LS_H   LS_W                  // sH: half[160] = 320B, pad to 512
#define LS_G   (LS_W + 512)          // sG: 640 floats
#define LS_TOT (LS_G + 2560)

// k-iter uses h-rows 8k..8k+7 (1 broadcast LDS.128) and pairs 4k..4k+3.
#define ACCR(k) { \
    uint4 hv = sH4[(k)]; \
    const __half2* hp = (const __half2*)&hv; \
    s = __hfma2(rw[4*(k)+0], hp[0], s); \
    s = __hfma2(rw[4*(k)+1], hp[1], s); \
    s = __hfma2(rw[4*(k)+2], hp[2], s); \
    s = __hfma2(rw[4*(k)+3], hp[3], s); }

#define ACCS(k) { \
    uint4 hv = sH4[(k)]; \
    const __half2* hp = (const __half2*)&hv; \
    uint4 wv = wqp[((k) - 14) * 640]; \
    s = __hfma2(*(__half2*)&wv.x, hp[0], s); \
    s = __hfma2(*(__half2*)&wv.y, hp[1], s); \
    s = __hfma2(*(__half2*)&wv.z, hp[2], s); \
    s = __hfma2(*(__half2*)&wv.w, hp[3], s); }

#define CHUNK_FLUSH { float2 f2 = __half22float2(s); acc += f2.x; acc += f2.y; }

__global__ __launch_bounds__(640, 1) void k_lstm(int stage, float* __restrict__ outp,
                                                 int to_bctf) {
    extern __shared__ char smem[];
    uint4*  sW4 = (uint4*)smem;
    __half* sHh = (__half*)(smem + LS_H);
    float*  sG  = (float*)(smem + LS_G);
    const uint4* sH4 = (const uint4*)sHh;

    int b = blockIdx.x, g = blockIdx.y;
    int tid = threadIdx.x, p = tid;

    const __half2* gw = g_wh2 + (size_t)stage * 102400 + (size_t)g * 51200;
    const unsigned* gwu = (const unsigned*)gw;

    // pairs 0..55 into registers
    __half2 rw[56];
#pragma unroll
    for (int j = 0; j < 56; j++) rw[j] = gw[j * 640 + p];

    // pairs 56..79 quad-packed into smem: sW4[k][p], k=0..5 covers pairs 56+4k..+3
    for (int i = tid; i < 3840; i += 640) {
        int k = i / 640, pp = i - k * 640;
        int q0 = 56 + 4 * k;
        uint4 v;
        v.x = gwu[(q0 + 0) * 640 + pp];
        v.y = gwu[(q0 + 1) * 640 + pp];
        v.z = gwu[(q0 + 2) * 640 + pp];
        v.w = gwu[(q0 + 3) * 640 + pp];
        sW4[k * 640 + pp] = v;
    }
    if (tid < 160) sHh[tid] = __float2half(0.f);
    __syncthreads();

    const float* xp = g_xproj + (size_t)b * 1000 * 1280 + g * 640 + p;
    float cst = 0.f;
    size_t obase = 0;
    if (tid < 160) {
        int d = g * 160 + tid;
        if (to_bctf) obase = (size_t)b * 320000 + (size_t)(d / 5) * 5000 + (d % 5);
        else         obase = (size_t)b * 320000 + d;
    }

    const uint4* wqp = sW4 + p;
    float xn = xp[0];

    for (int t = 0; t < 1000; t++) {
        float acc = xn;
        if (t + 1 < 1000) xn = xp[(size_t)(t + 1) * 1280];

        __half2 s;
        // 10 chunks of 16 rows (2 k-iters), fp16 accumulate within chunk
        s = __float2half2_rn(0.f); ACCR(0);  ACCR(1);  CHUNK_FLUSH;
        s = __float2half2_rn(0.f); ACCR(2);  ACCR(3);  CHUNK_FLUSH;
        s = __float2half2_rn(0.f); ACCR(4);  ACCR(5);  CHUNK_FLUSH;
        s = __float2half2_rn(0.f); ACCR(6);  ACCR(7);  CHUNK_FLUSH;
        s = __float2half2_rn(0.f); ACCR(8);  ACCR(9);  CHUNK_FLUSH;
        s = __float2half2_rn(0.f); ACCR(10); ACCR(11); CHUNK_FLUSH;
        s = __float2half2_rn(0.f); ACCR(12); ACCR(13); CHUNK_FLUSH;
        s = __float2half2_rn(0.f); ACCS(14); ACCS(15); CHUNK_FLUSH;
        s = __float2half2_rn(0.f); ACCS(16); ACCS(17); CHUNK_FLUSH;
        s = __float2half2_rn(0.f); ACCS(18); ACCS(19); CHUNK_FLUSH;

        sG[p] = acc;
        __syncthreads();

        if (tid < 160) {
            float gi = sG[tid], gf = sG[160 + tid], gg = sG[320 + tid], go = sG[480 + tid];
            float iv = __fdividef(1.f, 1.f + __expf(-gi));
            float fv = __fdividef(1.f, 1.f + __expf(-gf));
            float gv = 1.f - __fdividef(2.f, 1.f + __expf(2.f * gg));
            float ov = __fdividef(1.f, 1.f + __expf(-go));
            cst = fv * cst + iv * gv;
            float tc = 1.f - __fdividef(2.f, 1.f + __expf(2.f * cst));
            float hv = ov * tc;
            sHh[tid] = __float2half(hv);
            if (to_bctf) outp[obase + (size_t)t * 5] = hv;
            else         g_out1h[obase + (size_t)t * 320] = __float2half(hv);
        }
        __syncthreads();
    }
}

// ---------------- launcher ----------------
extern "C" void kernel_launch(void* const* d_in, const int* in_sizes, int n_in,
                              void* d_out, int out_size) {
    const float* input = (const float*)d_in[0];
    const float* Wih1  = (const float*)d_in[1];
    const float* Whh1  = (const float*)d_in[2];
    const float* b1    = (const float*)d_in[3];
    const float* Wih2  = (const float*)d_in[4];
    const float* Whh2  = (const float*)d_in[5];
    const float* b2    = (const float*)d_in[6];
    const int*   snd   = (const int*)d_in[7];
    float* out = (float*)d_out;

    cudaFuncSetAttribute(k_gemm, cudaFuncAttributeMaxDynamicSharedMemorySize, GEMM_SMEM);
    cudaFuncSetAttribute(k_lstm, cudaFuncAttributeMaxDynamicSharedMemorySize, LS_TOT);

    k_convert<<<(409600 + 255) / 256, 256>>>(Wih1, Wih2, Whh1, Whh2);
    k_transpose<<<dim3(64, 20), 256>>>(input);

    // stage 1
    k_gemm<<<dim3(500, 2, 2), 256, GEMM_SMEM>>>(0, b1);
    k_lstm<<<dim3(64, 2), 640, LS_TOT>>>(0, out, 0);

    // stage 2
    k_gather<<<1000, 256>>>(snd);
    k_gemm<<<dim3(500, 2, 2), 256, GEMM_SMEM>>>(1, b2);
    k_lstm<<<dim3(64, 2), 640, LS_TOT>>>(1, out, 1);
}